// round 13
// baseline (speedup 1.0000x reference)
#include <cuda_runtime.h>

#define NSEQ 8192
#define HID 50
#define EDIM 300
#define PDIM 50
#define K0 350
#define K1 100
#define CH 32
#define BURN 64
#define NCHUNK (NSEQ / CH)

typedef unsigned long long u64;

// -------- scratch (no allocations allowed) --------
__device__ float g_P0[2u * NSEQ * 200];  // layer0 input-proj gates [dir][t][g]
__device__ float g_H0[NSEQ * K1];        // layer0 output concat [t][fwd50|bwd50]
__device__ float g_P1[2u * NSEQ * 200];
__device__ float g_H1[NSEQ * K1];
__device__ float g_ai[NSEQ];
__device__ float g_sj[NSEQ];

// -------- helpers --------
__device__ __forceinline__ u64 pk2(float lo, float hi) {
    u64 r;
    asm("mov.b64 %0,{%1,%2};" : "=l"(r) : "f"(lo), "f"(hi));
    return r;
}
__device__ __forceinline__ void upk2(u64 v, float& lo, float& hi) {
    asm("mov.b64 {%0,%1},%2;" : "=f"(lo), "=f"(hi) : "l"(v));
}
__device__ __forceinline__ u64 ffma2(u64 a, u64 b, u64 c) {
    u64 d;
    asm("fma.rn.f32x2 %0,%1,%2,%3;" : "=l"(d) : "l"(a), "l"(b), "l"(c));
    return d;
}
__device__ __forceinline__ u64 addf2(u64 a, u64 b) {
    u64 d;
    asm("add.rn.f32x2 %0,%1,%2;" : "=l"(d) : "l"(a), "l"(b));
    return d;
}
// accurate activations (EX2 + RCP, ~1e-6 rel): safe across the scan
__device__ __forceinline__ float sig_f(float x) {
    return __fdividef(1.f, 1.f + __expf(-x));
}
__device__ __forceinline__ float tanh_f(float x) {
    return __fdividef(2.f, 1.f + __expf(-2.f * x)) - 1.f;
}

// -------- input projection GEMM: P[dir][t][g] = b[g] + sum_k x[t][k]*W[g][k] --------
template <int KD, int TOK, int LAYER>
__global__ __launch_bounds__(400) void pre_gemm(
    const int* __restrict__ tok, const float* __restrict__ emb,
    const float* __restrict__ pos, const float* __restrict__ wf,
    const float* __restrict__ wb, const float* __restrict__ bf,
    const float* __restrict__ bb) {
    constexpr int XW = TOK + 4;  // keeps each row 16B-aligned (XW%4==0)
    __shared__ __align__(16) float xs[KD][XW];
    float* Pout = LAYER ? g_P1 : g_P0;
    int t0 = blockIdx.x * TOK;

    for (int idx = threadIdx.x; idx < KD * TOK; idx += 400) {
        int tt = idx / KD, k = idx - tt * KD;
        int t = t0 + tt;
        float v;
        if (LAYER == 0)
            v = (k < EDIM) ? emb[(size_t)tok[t] * EDIM + k]
                           : pos[t * PDIM + (k - EDIM)];
        else
            v = g_H0[t * K1 + k];
        xs[k][tt] = v;
    }
    __syncthreads();

    int o = threadIdx.x;
    int d = (o >= 200) ? 1 : 0;
    int oo = d ? o - 200 : o;
    const float* wr = (d ? wb : wf) + oo * KD;
    float bias = (d ? bb : bf)[oo];

    u64 acc[TOK / 2];
#pragma unroll
    for (int i = 0; i < TOK / 2; i++) acc[i] = 0ull;

    for (int kk = 0; kk < KD; kk += 2) {
        float2 wp = __ldg((const float2*)(wr + kk));
        u64 w0 = pk2(wp.x, wp.x);
        u64 w1 = pk2(wp.y, wp.y);
        const ulonglong2* x0 = (const ulonglong2*)(&xs[kk][0]);
        const ulonglong2* x1 = (const ulonglong2*)(&xs[kk + 1][0]);
#pragma unroll
        for (int i = 0; i < TOK / 4; i++) {
            ulonglong2 v0 = x0[i];
            acc[2 * i] = ffma2(w0, v0.x, acc[2 * i]);
            acc[2 * i + 1] = ffma2(w0, v0.y, acc[2 * i + 1]);
        }
#pragma unroll
        for (int i = 0; i < TOK / 4; i++) {
            ulonglong2 v1 = x1[i];
            acc[2 * i] = ffma2(w1, v1.x, acc[2 * i]);
            acc[2 * i + 1] = ffma2(w1, v1.y, acc[2 * i + 1]);
        }
    }

    float* Po = Pout + ((size_t)d * NSEQ + t0) * 200 + oo;
#pragma unroll
    for (int i = 0; i < TOK / 2; i++) {
        float a, b2;
        upk2(acc[i], a, b2);
        Po[(2 * i) * 200] = a + bias;
        Po[(2 * i + 1) * 200] = b2 + bias;
    }
}

// -------- chunked LSTM scan with burn-in --------
// grid = 2*NCHUNK blocks: block = (chunk, dir). 224 threads, 4 blocks/SM.
// thread 4k+q computes gate g = q*50+k (PyTorch i,f,g,o order).
// W_hh lives in smem thread-indexed (wsm[j*224+tid]) -> conflict-free LDS.64,
// frees ~52 regs/thread so 4 blocks fit per SM (latency hiding for the
// serial-critical-path-bound step).
template <int LAYER>
__global__ __launch_bounds__(224, 4) void lstm_scan(
    const float* __restrict__ whf, const float* __restrict__ whb) {
    const float* P = LAYER ? g_P1 : g_P0;
    float* Hout = LAYER ? g_H1 : g_H0;

    int dir = blockIdx.x & 1;
    int chunk = blockIdx.x >> 1;
    int tid = threadIdx.x;
    int k = tid >> 2;
    if (k > HID - 1) k = HID - 1;  // clamp spare threads (no writes)
    int q = tid & 3;
    bool lead = (q == 0) && (tid < 4 * HID);

    __shared__ __align__(16) u64 wsm[25 * 224];   // 44.8 KB
    __shared__ __align__(16) float hbuf[2][64];   // double-buffered h

    // load this thread's W_hh row (50 floats = 25 u64) into its smem column
    {
        int g = (tid < 4 * HID) ? (q * HID + k) : 0;
        const u64* wrow = (const u64*)((dir ? whb : whf) + g * HID);
#pragma unroll
        for (int j = 0; j < 25; j++) wsm[j * 224 + tid] = wrow[j];
    }
    if (tid < 64) { hbuf[0][tid] = 0.f; hbuf[1][tid] = 0.f; }
    float c = 0.f;

    int lo = chunk * CH, hi = lo + CH;
    int t_start, ns;
    if (!dir) {
        t_start = lo - BURN;
        if (t_start < 0) t_start = 0;
        ns = hi - t_start;
    } else {
        t_start = hi - 1 + BURN;
        if (t_start > NSEQ - 1) t_start = NSEQ - 1;
        ns = t_start - lo + 1;
    }
    int sgn = dir ? -1 : 1;
    const float* Pg = P + (size_t)dir * NSEQ * 200 + (q * HID + k);
    int colbase = dir * HID + k;
    __syncthreads();

    auto ldpre = [&](int s) -> float {
        return (s < ns) ? Pg[(size_t)(t_start + sgn * s) * 200] : 0.f;
    };
    auto step = [&](int S, float pre) {
        const ulonglong2* hp = (const ulonglong2*)hbuf[S & 1];
        const u64* wp = wsm + tid;
        // 4 independent accumulator chains; LDS.128 for h, LDS.64 for w
        u64 a0 = pk2(pre, 0.f), a1 = 0ull, a2 = 0ull, a3 = 0ull;
#pragma unroll
        for (int i = 0; i < 6; i++) {
            ulonglong2 h0 = hp[2 * i];
            ulonglong2 h1 = hp[2 * i + 1];
            a0 = ffma2(wp[(4 * i + 0) * 224], h0.x, a0);
            a1 = ffma2(wp[(4 * i + 1) * 224], h0.y, a1);
            a2 = ffma2(wp[(4 * i + 2) * 224], h1.x, a2);
            a3 = ffma2(wp[(4 * i + 3) * 224], h1.y, a3);
        }
        a0 = ffma2(wp[24 * 224], ((const u64*)hp)[24], a0);
        u64 s2 = addf2(addf2(a0, a1), addf2(a2, a3));
        float glo, ghi;
        upk2(s2, glo, ghi);
        float g = glo + ghi;
        // per-gate activation BEFORE exchange (off the serial chain)
        float a = (q == 2) ? tanh_f(g) : sig_f(g);
        float af = __shfl_down_sync(0xffffffffu, a, 1);
        float ag = __shfl_down_sync(0xffffffffu, a, 2);
        float ao = __shfl_down_sync(0xffffffffu, a, 3);
        if (lead) {  // a = sig(i), af = sig(f), ag = tanh(g), ao = sig(o)
            c = af * c + a * ag;
            float hn = ao * tanh_f(c);
            hbuf[(S + 1) & 1][k] = hn;
            int t = t_start + sgn * S;
            if (t >= lo && t < hi) Hout[t * K1 + colbase] = hn;
        }
        __syncthreads();
    };

    float preA = ldpre(0);
    float preB = ldpre(1);
    for (int s = 0; s < ns; s += 2) {  // 2-deep prefetch of pre-gates stream
        step(s, preA);
        preA = ldpre(s + 2);
        if (s + 1 < ns) {
            step(s + 1, preB);
            preB = ldpre(s + 3);
        }
    }
}

// -------- per-token score vectors: ai[t]=h.w[:100]+b, sj[t]=h.w[100:] --------
__global__ __launch_bounds__(256) void score_vec(const float* __restrict__ mw,
                                                 const float* __restrict__ mb) {
    int t = blockIdx.x * 256 + threadIdx.x;
    const float* h = g_H1 + t * K1;
    float s1 = 0.f, s2 = 0.f;
#pragma unroll
    for (int dd = 0; dd < K1; dd++) {
        float hv = h[dd];
        s1 += hv * mw[dd];
        s2 += hv * mw[K1 + dd];
    }
    g_ai[t] = s1 + mb[0];
    g_sj[t] = s2;
}

// -------- NxN output: out[i][j] = (j>i) ? tanh(ai[i]+sj[j]) : 0 --------
// 4 rows per block: amortizes the g_sj read across 4 output rows.
__global__ __launch_bounds__(256) void score_mat(float* __restrict__ out) {
    int i0 = blockIdx.x * 4;
    float a0 = g_ai[i0], a1 = g_ai[i0 + 1], a2 = g_ai[i0 + 2], a3 = g_ai[i0 + 3];
    const float4* sj4 = (const float4*)g_sj;
#pragma unroll
    for (int it = 0; it < 8; it++) {
        int j4 = threadIdx.x + it * 256;
        int col = j4 << 2;
        float4 s;
        bool anylive = (col + 3 > i0);
        if (anylive) s = sj4[j4];
#pragma unroll
        for (int r = 0; r < 4; r++) {
            int i = i0 + r;
            float a = (r == 0) ? a0 : (r == 1) ? a1 : (r == 2) ? a2 : a3;
            float4 v;
            if (col + 3 <= i) {
                v.x = v.y = v.z = v.w = 0.f;
            } else {
                v.x = (col > i) ? tanh_f(a + s.x) : 0.f;
                v.y = (col + 1 > i) ? tanh_f(a + s.y) : 0.f;
                v.z = (col + 2 > i) ? tanh_f(a + s.z) : 0.f;
                v.w = (col + 3 > i) ? tanh_f(a + s.w) : 0.f;
            }
            *(float4*)(out + (size_t)i * NSEQ + col) = v;
        }
    }
}

extern "C" void kernel_launch(void* const* d_in, const int* in_sizes, int n_in,
                              void* d_out, int out_size) {
    const int* tok = (const int*)d_in[0];
    const float* pos = (const float*)d_in[1];
    const float* emb = (const float*)d_in[2];
    const float* wih0f = (const float*)d_in[3];
    const float* whh0f = (const float*)d_in[4];
    const float* b0f = (const float*)d_in[5];
    const float* wih0b = (const float*)d_in[6];
    const float* whh0b = (const float*)d_in[7];
    const float* b0b = (const float*)d_in[8];
    const float* wih1f = (const float*)d_in[9];
    const float* whh1f = (const float*)d_in[10];
    const float* b1f = (const float*)d_in[11];
    const float* wih1b = (const float*)d_in[12];
    const float* whh1b = (const float*)d_in[13];
    const float* b1b = (const float*)d_in[14];
    const float* mw = (const float*)d_in[15];
    const float* mb = (const float*)d_in[16];
    float* out = (float*)d_out;

    pre_gemm<K0, 32, 0><<<NSEQ / 32, 400>>>(tok, emb, pos, wih0f, wih0b, b0f, b0b);
    lstm_scan<0><<<2 * NCHUNK, 224>>>(whh0f, whh0b);
    pre_gemm<K1, 64, 1><<<NSEQ / 64, 400>>>(tok, emb, pos, wih1f, wih1b, b1f, b1b);
    lstm_scan<1><<<2 * NCHUNK, 224>>>(whh1f, whh1b);
    score_vec<<<NSEQ / 256, 256>>>(mw, mb);
    score_mat<<<NSEQ / 4, 256>>>(out);
}

// round 14
// speedup vs baseline: 1.4162x; 1.4162x over previous
#include <cuda_runtime.h>

#define NSEQ 8192
#define HID 50
#define EDIM 300
#define PDIM 50
#define K0 350
#define K1 100
#define CH 64
#define BURN 48
#define NCHUNK (NSEQ / CH)

typedef unsigned long long u64;

// -------- scratch (no allocations allowed) --------
__device__ float g_P0[2u * NSEQ * 200];  // layer0 input-proj gates [dir][t][g]
__device__ float g_H0[NSEQ * K1];        // layer0 output concat [t][fwd50|bwd50]
__device__ float g_P1[2u * NSEQ * 200];
__device__ float g_H1[NSEQ * K1];
__device__ float g_ai[NSEQ];
__device__ float g_sj[NSEQ];

// -------- helpers --------
__device__ __forceinline__ u64 pk2(float lo, float hi) {
    u64 r;
    asm("mov.b64 %0,{%1,%2};" : "=l"(r) : "f"(lo), "f"(hi));
    return r;
}
__device__ __forceinline__ void upk2(u64 v, float& lo, float& hi) {
    asm("mov.b64 {%0,%1},%2;" : "=f"(lo), "=f"(hi) : "l"(v));
}
__device__ __forceinline__ u64 ffma2(u64 a, u64 b, u64 c) {
    u64 d;
    asm("fma.rn.f32x2 %0,%1,%2,%3;" : "=l"(d) : "l"(a), "l"(b), "l"(c));
    return d;
}
__device__ __forceinline__ u64 addf2(u64 a, u64 b) {
    u64 d;
    asm("add.rn.f32x2 %0,%1,%2;" : "=l"(d) : "l"(a), "l"(b));
    return d;
}
// accurate activations (EX2 + RCP, ~1e-6 rel): safe across the scan
__device__ __forceinline__ float sig_f(float x) {
    return __fdividef(1.f, 1.f + __expf(-x));
}
__device__ __forceinline__ float tanh_f(float x) {
    return __fdividef(2.f, 1.f + __expf(-2.f * x)) - 1.f;
}

// -------- input projection GEMM: P[dir][t][g] = b[g] + sum_k x[t][k]*W[g][k] --------
template <int KD, int TOK, int LAYER>
__global__ __launch_bounds__(400) void pre_gemm(
    const int* __restrict__ tok, const float* __restrict__ emb,
    const float* __restrict__ pos, const float* __restrict__ wf,
    const float* __restrict__ wb, const float* __restrict__ bf,
    const float* __restrict__ bb) {
    constexpr int XW = TOK + 4;  // keeps each row 16B-aligned (XW%4==0)
    __shared__ __align__(16) float xs[KD][XW];
    float* Pout = LAYER ? g_P1 : g_P0;
    int t0 = blockIdx.x * TOK;

    for (int idx = threadIdx.x; idx < KD * TOK; idx += 400) {
        int tt = idx / KD, k = idx - tt * KD;
        int t = t0 + tt;
        float v;
        if (LAYER == 0)
            v = (k < EDIM) ? emb[(size_t)tok[t] * EDIM + k]
                           : pos[t * PDIM + (k - EDIM)];
        else
            v = g_H0[t * K1 + k];
        xs[k][tt] = v;
    }
    __syncthreads();

    int o = threadIdx.x;
    int d = (o >= 200) ? 1 : 0;
    int oo = d ? o - 200 : o;
    const float* wr = (d ? wb : wf) + oo * KD;
    float bias = (d ? bb : bf)[oo];

    u64 acc[TOK / 2];
#pragma unroll
    for (int i = 0; i < TOK / 2; i++) acc[i] = 0ull;

    for (int kk = 0; kk < KD; kk += 2) {
        float2 wp = __ldg((const float2*)(wr + kk));
        u64 w0 = pk2(wp.x, wp.x);
        u64 w1 = pk2(wp.y, wp.y);
        const ulonglong2* x0 = (const ulonglong2*)(&xs[kk][0]);
        const ulonglong2* x1 = (const ulonglong2*)(&xs[kk + 1][0]);
#pragma unroll
        for (int i = 0; i < TOK / 4; i++) {
            ulonglong2 v0 = x0[i];
            acc[2 * i] = ffma2(w0, v0.x, acc[2 * i]);
            acc[2 * i + 1] = ffma2(w0, v0.y, acc[2 * i + 1]);
        }
#pragma unroll
        for (int i = 0; i < TOK / 4; i++) {
            ulonglong2 v1 = x1[i];
            acc[2 * i] = ffma2(w1, v1.x, acc[2 * i]);
            acc[2 * i + 1] = ffma2(w1, v1.y, acc[2 * i + 1]);
        }
    }

    float* Po = Pout + ((size_t)d * NSEQ + t0) * 200 + oo;
#pragma unroll
    for (int i = 0; i < TOK / 2; i++) {
        float a, b2;
        upk2(acc[i], a, b2);
        Po[(2 * i) * 200] = a + bias;
        Po[(2 * i + 1) * 200] = b2 + bias;
    }
}

// -------- chunked LSTM scan with burn-in --------
// grid = 2*NCHUNK blocks: block = (chunk, dir). 224 threads, 2 blocks/SM.
// thread 4k+q computes gate g = q*50+k (PyTorch i,f,g,o order).
// W_hh register-resident: the per-step weight operand stream (40KB/step/chain)
// exceeds smem crossbar budget — only the RF can feed it (R13 lesson).
template <int LAYER>
__global__ __launch_bounds__(224, 2) void lstm_scan(
    const float* __restrict__ whf, const float* __restrict__ whb) {
    const float* P = LAYER ? g_P1 : g_P0;
    float* Hout = LAYER ? g_H1 : g_H0;

    int dir = blockIdx.x & 1;
    int chunk = blockIdx.x >> 1;
    int tid = threadIdx.x;
    int k = tid >> 2;
    if (k > HID - 1) k = HID - 1;  // clamp spare threads (no writes)
    int q = tid & 3;
    bool lead = (q == 0) && (tid < 4 * HID);

    const float* whh = dir ? whb : whf;
    u64 wv[HID / 2 + 1];  // 25 used
    {
        const u64* wrow = (const u64*)(whh + (q * HID + k) * HID);
#pragma unroll
        for (int j = 0; j < HID / 2; j++) wv[j] = wrow[j];
    }

    __shared__ __align__(16) float hbuf[2][64];  // double-buffered h
    if (tid < 64) { hbuf[0][tid] = 0.f; hbuf[1][tid] = 0.f; }
    float c = 0.f;

    int lo = chunk * CH, hi = lo + CH;
    int t_start, ns;
    if (!dir) {
        t_start = lo - BURN;
        if (t_start < 0) t_start = 0;
        ns = hi - t_start;
    } else {
        t_start = hi - 1 + BURN;
        if (t_start > NSEQ - 1) t_start = NSEQ - 1;
        ns = t_start - lo + 1;
    }
    int sgn = dir ? -1 : 1;
    const float* Pg = P + (size_t)dir * NSEQ * 200 + (q * HID + k);
    int colbase = dir * HID + k;
    __syncthreads();

    auto ldpre = [&](int s) -> float {
        return (s < ns) ? Pg[(size_t)(t_start + sgn * s) * 200] : 0.f;
    };
    auto step = [&](int S, float pre) {
        const ulonglong2* hp = (const ulonglong2*)hbuf[S & 1];
        // 4 independent accumulator chains; LDS.128 for h
        u64 a0 = pk2(pre, 0.f), a1 = 0ull, a2 = 0ull, a3 = 0ull;
#pragma unroll
        for (int i = 0; i < 12; i += 2) {
            ulonglong2 h0 = hp[i];
            ulonglong2 h1 = hp[i + 1];
            a0 = ffma2(wv[2 * i], h0.x, a0);
            a1 = ffma2(wv[2 * i + 1], h0.y, a1);
            a2 = ffma2(wv[2 * i + 2], h1.x, a2);
            a3 = ffma2(wv[2 * i + 3], h1.y, a3);
        }
        a0 = ffma2(wv[24], ((const u64*)hp)[24], a0);
        u64 s2 = addf2(addf2(a0, a1), addf2(a2, a3));
        float glo, ghi;
        upk2(s2, glo, ghi);
        float g = glo + ghi;
        // per-gate activation BEFORE exchange (off the serial chain)
        float a = (q == 2) ? tanh_f(g) : sig_f(g);
        float af = __shfl_down_sync(0xffffffffu, a, 1);
        float ag = __shfl_down_sync(0xffffffffu, a, 2);
        float ao = __shfl_down_sync(0xffffffffu, a, 3);
        if (lead) {  // a = sig(i), af = sig(f), ag = tanh(g), ao = sig(o)
            c = af * c + a * ag;
            float hn = ao * tanh_f(c);
            hbuf[(S + 1) & 1][k] = hn;
            int t = t_start + sgn * S;
            if (t >= lo && t < hi) Hout[t * K1 + colbase] = hn;
        }
        __syncthreads();
    };

    float preA = ldpre(0);
    float preB = ldpre(1);
    for (int s = 0; s < ns; s += 2) {  // 2-deep prefetch of pre-gates stream
        step(s, preA);
        preA = ldpre(s + 2);
        if (s + 1 < ns) {
            step(s + 1, preB);
            preB = ldpre(s + 3);
        }
    }
}

// -------- per-token score vectors: ai[t]=h.w[:100]+b, sj[t]=h.w[100:] --------
__global__ __launch_bounds__(256) void score_vec(const float* __restrict__ mw,
                                                 const float* __restrict__ mb) {
    int t = blockIdx.x * 256 + threadIdx.x;
    const float* h = g_H1 + t * K1;
    float s1 = 0.f, s2 = 0.f;
#pragma unroll
    for (int dd = 0; dd < K1; dd++) {
        float hv = h[dd];
        s1 += hv * mw[dd];
        s2 += hv * mw[K1 + dd];
    }
    g_ai[t] = s1 + mb[0];
    g_sj[t] = s2;
}

// -------- NxN output: out[i][j] = (j>i) ? tanh(ai[i]+sj[j]) : 0 --------
// 4 rows per block: amortizes the g_sj read across 4 output rows.
__global__ __launch_bounds__(256) void score_mat(float* __restrict__ out) {
    int i0 = blockIdx.x * 4;
    float a0 = g_ai[i0], a1 = g_ai[i0 + 1], a2 = g_ai[i0 + 2], a3 = g_ai[i0 + 3];
    const float4* sj4 = (const float4*)g_sj;
#pragma unroll
    for (int it = 0; it < 8; it++) {
        int j4 = threadIdx.x + it * 256;
        int col = j4 << 2;
        float4 s;
        bool anylive = (col + 3 > i0);
        if (anylive) s = sj4[j4];
#pragma unroll
        for (int r = 0; r < 4; r++) {
            int i = i0 + r;
            float a = (r == 0) ? a0 : (r == 1) ? a1 : (r == 2) ? a2 : a3;
            float4 v;
            if (col + 3 <= i) {
                v.x = v.y = v.z = v.w = 0.f;
            } else {
                v.x = (col > i) ? tanh_f(a + s.x) : 0.f;
                v.y = (col + 1 > i) ? tanh_f(a + s.y) : 0.f;
                v.z = (col + 2 > i) ? tanh_f(a + s.z) : 0.f;
                v.w = (col + 3 > i) ? tanh_f(a + s.w) : 0.f;
            }
            *(float4*)(out + (size_t)i * NSEQ + col) = v;
        }
    }
}

extern "C" void kernel_launch(void* const* d_in, const int* in_sizes, int n_in,
                              void* d_out, int out_size) {
    const int* tok = (const int*)d_in[0];
    const float* pos = (const float*)d_in[1];
    const float* emb = (const float*)d_in[2];
    const float* wih0f = (const float*)d_in[3];
    const float* whh0f = (const float*)d_in[4];
    const float* b0f = (const float*)d_in[5];
    const float* wih0b = (const float*)d_in[6];
    const float* whh0b = (const float*)d_in[7];
    const float* b0b = (const float*)d_in[8];
    const float* wih1f = (const float*)d_in[9];
    const float* whh1f = (const float*)d_in[10];
    const float* b1f = (const float*)d_in[11];
    const float* wih1b = (const float*)d_in[12];
    const float* whh1b = (const float*)d_in[13];
    const float* b1b = (const float*)d_in[14];
    const float* mw = (const float*)d_in[15];
    const float* mb = (const float*)d_in[16];
    float* out = (float*)d_out;

    pre_gemm<K0, 32, 0><<<NSEQ / 32, 400>>>(tok, emb, pos, wih0f, wih0b, b0f, b0b);
    lstm_scan<0><<<2 * NCHUNK, 224>>>(whh0f, whh0b);
    pre_gemm<K1, 64, 1><<<NSEQ / 64, 400>>>(tok, emb, pos, wih1f, wih1b, b1f, b1b);
    lstm_scan<1><<<2 * NCHUNK, 224>>>(whh1f, whh1b);
    score_vec<<<NSEQ / 256, 256>>>(mw, mb);
    score_mat<<<NSEQ / 4, 256>>>(out);
}

// round 15
// speedup vs baseline: 1.4409x; 1.0174x over previous
#include <cuda_runtime.h>

#define NSEQ 8192
#define HID 50
#define EDIM 300
#define PDIM 50
#define K0 350
#define K1 100
#define CH 64
#define BURN 40
#define NCHUNK (NSEQ / CH)
#define ZBLK 1024

typedef unsigned long long u64;

// -------- scratch (no allocations allowed) --------
__device__ float g_P0[2u * NSEQ * 200];  // layer0 input-proj gates [dir][t][g]
__device__ float g_H0[NSEQ * K1];        // layer0 output concat [t][fwd50|bwd50]
__device__ float g_P1[2u * NSEQ * 200];
__device__ float g_H1[NSEQ * K1];
__device__ float g_ai[NSEQ];
__device__ float g_sj[NSEQ];

// -------- helpers --------
__device__ __forceinline__ u64 pk2(float lo, float hi) {
    u64 r;
    asm("mov.b64 %0,{%1,%2};" : "=l"(r) : "f"(lo), "f"(hi));
    return r;
}
__device__ __forceinline__ void upk2(u64 v, float& lo, float& hi) {
    asm("mov.b64 {%0,%1},%2;" : "=f"(lo), "=f"(hi) : "l"(v));
}
__device__ __forceinline__ u64 ffma2(u64 a, u64 b, u64 c) {
    u64 d;
    asm("fma.rn.f32x2 %0,%1,%2,%3;" : "=l"(d) : "l"(a), "l"(b), "l"(c));
    return d;
}
__device__ __forceinline__ u64 addf2(u64 a, u64 b) {
    u64 d;
    asm("add.rn.f32x2 %0,%1,%2;" : "=l"(d) : "l"(a), "l"(b));
    return d;
}
// accurate activations (EX2 + RCP, ~1e-6 rel): safe across the scan
__device__ __forceinline__ float sig_f(float x) {
    return __fdividef(1.f, 1.f + __expf(-x));
}
__device__ __forceinline__ float tanh_f(float x) {
    return __fdividef(2.f, 1.f + __expf(-2.f * x)) - 1.f;
}

// -------- input projection GEMM: P[dir][t][g] = b[g] + sum_k x[t][k]*W[g][k] --------
// LAYER 0 launch carries ZBLK extra interleaved blocks (1 compute : 4 zero)
// that zero-fill the lower triangle of `out` — DRAM stream hidden under the
// FMA-bound GEMM (DRAM was at 2%).
template <int KD, int TOK, int LAYER>
__global__ __launch_bounds__(400) void pre_gemm(
    const int* __restrict__ tok, const float* __restrict__ emb,
    const float* __restrict__ pos, const float* __restrict__ wf,
    const float* __restrict__ wb, const float* __restrict__ bf,
    const float* __restrict__ bb, float* __restrict__ zout) {
    int cb;  // compute-block id
    if (LAYER == 0) {
        int bx = blockIdx.x;
        if (bx % 5 != 0) {
            // ---- zero-fill block: rows zb, zb+ZBLK, ... (8 rows) ----
            int zb = bx - bx / 5 - 1;
            float4 z = make_float4(0.f, 0.f, 0.f, 0.f);
#pragma unroll
            for (int rr = 0; rr < NSEQ / ZBLK; rr++) {
                int i = zb + rr * ZBLK;
                int n4 = (i + 1) >> 2;  // float4-aligned prefix, all cols <= i
                float4* row = (float4*)(zout + (size_t)i * NSEQ);
                for (int c = threadIdx.x; c < n4; c += 400) row[c] = z;
            }
            return;
        }
        cb = bx / 5;
    } else {
        cb = blockIdx.x;
    }

    constexpr int XW = TOK + 4;  // keeps each row 16B-aligned (XW%4==0)
    __shared__ __align__(16) float xs[KD][XW];
    float* Pout = LAYER ? g_P1 : g_P0;
    int t0 = cb * TOK;

    for (int idx = threadIdx.x; idx < KD * TOK; idx += 400) {
        int tt = idx / KD, k = idx - tt * KD;
        int t = t0 + tt;
        float v;
        if (LAYER == 0)
            v = (k < EDIM) ? emb[(size_t)tok[t] * EDIM + k]
                           : pos[t * PDIM + (k - EDIM)];
        else
            v = g_H0[t * K1 + k];
        xs[k][tt] = v;
    }
    __syncthreads();

    int o = threadIdx.x;
    int d = (o >= 200) ? 1 : 0;
    int oo = d ? o - 200 : o;
    const float* wr = (d ? wb : wf) + oo * KD;
    float bias = (d ? bb : bf)[oo];

    u64 acc[TOK / 2];
#pragma unroll
    for (int i = 0; i < TOK / 2; i++) acc[i] = 0ull;

    int kk = 0;
    // main loop: 4 k-values per iter, both weight LDGs issued up front (MLP>=2)
    for (; kk + 4 <= KD; kk += 4) {
        float2 wpA = __ldg((const float2*)(wr + kk));
        float2 wpB = __ldg((const float2*)(wr + kk + 2));
        u64 w0 = pk2(wpA.x, wpA.x);
        u64 w1 = pk2(wpA.y, wpA.y);
        u64 w2 = pk2(wpB.x, wpB.x);
        u64 w3 = pk2(wpB.y, wpB.y);
        const ulonglong2* x0 = (const ulonglong2*)(&xs[kk][0]);
        const ulonglong2* x1 = (const ulonglong2*)(&xs[kk + 1][0]);
        const ulonglong2* x2 = (const ulonglong2*)(&xs[kk + 2][0]);
        const ulonglong2* x3 = (const ulonglong2*)(&xs[kk + 3][0]);
#pragma unroll
        for (int i = 0; i < TOK / 4; i++) {
            ulonglong2 v0 = x0[i];
            acc[2 * i] = ffma2(w0, v0.x, acc[2 * i]);
            acc[2 * i + 1] = ffma2(w0, v0.y, acc[2 * i + 1]);
        }
#pragma unroll
        for (int i = 0; i < TOK / 4; i++) {
            ulonglong2 v1 = x1[i];
            acc[2 * i] = ffma2(w1, v1.x, acc[2 * i]);
            acc[2 * i + 1] = ffma2(w1, v1.y, acc[2 * i + 1]);
        }
#pragma unroll
        for (int i = 0; i < TOK / 4; i++) {
            ulonglong2 v2 = x2[i];
            acc[2 * i] = ffma2(w2, v2.x, acc[2 * i]);
            acc[2 * i + 1] = ffma2(w2, v2.y, acc[2 * i + 1]);
        }
#pragma unroll
        for (int i = 0; i < TOK / 4; i++) {
            ulonglong2 v3 = x3[i];
            acc[2 * i] = ffma2(w3, v3.x, acc[2 * i]);
            acc[2 * i + 1] = ffma2(w3, v3.y, acc[2 * i + 1]);
        }
    }
    for (; kk < KD; kk += 2) {  // remainder (KD=350 -> 2 left)
        float2 wp = __ldg((const float2*)(wr + kk));
        u64 w0 = pk2(wp.x, wp.x);
        u64 w1 = pk2(wp.y, wp.y);
        const ulonglong2* x0 = (const ulonglong2*)(&xs[kk][0]);
        const ulonglong2* x1 = (const ulonglong2*)(&xs[kk + 1][0]);
#pragma unroll
        for (int i = 0; i < TOK / 4; i++) {
            ulonglong2 v0 = x0[i];
            ulonglong2 v1 = x1[i];
            acc[2 * i] = ffma2(w0, v0.x, acc[2 * i]);
            acc[2 * i + 1] = ffma2(w0, v0.y, acc[2 * i + 1]);
            acc[2 * i] = ffma2(w1, v1.x, acc[2 * i]);
            acc[2 * i + 1] = ffma2(w1, v1.y, acc[2 * i + 1]);
        }
    }

    float* Po = Pout + ((size_t)d * NSEQ + t0) * 200 + oo;
#pragma unroll
    for (int i = 0; i < TOK / 2; i++) {
        float a, b2;
        upk2(acc[i], a, b2);
        Po[(2 * i) * 200] = a + bias;
        Po[(2 * i + 1) * 200] = b2 + bias;
    }
}

// -------- chunked LSTM scan with burn-in --------
// grid = 2*NCHUNK blocks: block = (chunk, dir). 224 threads, 2 blocks/SM.
// thread 4k+q computes gate g = q*50+k (PyTorch i,f,g,o order).
// W_hh register-resident: the per-step weight operand stream (40KB/step/chain)
// exceeds smem crossbar budget — only the RF can feed it (R13 lesson).
template <int LAYER>
__global__ __launch_bounds__(224, 2) void lstm_scan(
    const float* __restrict__ whf, const float* __restrict__ whb) {
    const float* P = LAYER ? g_P1 : g_P0;
    float* Hout = LAYER ? g_H1 : g_H0;

    int dir = blockIdx.x & 1;
    int chunk = blockIdx.x >> 1;
    int tid = threadIdx.x;
    int k = tid >> 2;
    if (k > HID - 1) k = HID - 1;  // clamp spare threads (no writes)
    int q = tid & 3;
    bool lead = (q == 0) && (tid < 4 * HID);

    const float* whh = dir ? whb : whf;
    u64 wv[HID / 2 + 1];  // 25 used
    {
        const u64* wrow = (const u64*)(whh + (q * HID + k) * HID);
#pragma unroll
        for (int j = 0; j < HID / 2; j++) wv[j] = wrow[j];
    }

    __shared__ __align__(16) float hbuf[2][64];  // double-buffered h
    if (tid < 64) { hbuf[0][tid] = 0.f; hbuf[1][tid] = 0.f; }
    float c = 0.f;

    int lo = chunk * CH, hi = lo + CH;
    int t_start, ns;
    if (!dir) {
        t_start = lo - BURN;
        if (t_start < 0) t_start = 0;
        ns = hi - t_start;
    } else {
        t_start = hi - 1 + BURN;
        if (t_start > NSEQ - 1) t_start = NSEQ - 1;
        ns = t_start - lo + 1;
    }
    int sgn = dir ? -1 : 1;
    const float* Pg = P + (size_t)dir * NSEQ * 200 + (q * HID + k);
    int colbase = dir * HID + k;
    __syncthreads();

    auto ldpre = [&](int s) -> float {
        return (s < ns) ? Pg[(size_t)(t_start + sgn * s) * 200] : 0.f;
    };
    auto step = [&](int S, float pre) {
        const ulonglong2* hp = (const ulonglong2*)hbuf[S & 1];
        // 4 independent accumulator chains; LDS.128 for h
        u64 a0 = pk2(pre, 0.f), a1 = 0ull, a2 = 0ull, a3 = 0ull;
#pragma unroll
        for (int i = 0; i < 12; i += 2) {
            ulonglong2 h0 = hp[i];
            ulonglong2 h1 = hp[i + 1];
            a0 = ffma2(wv[2 * i], h0.x, a0);
            a1 = ffma2(wv[2 * i + 1], h0.y, a1);
            a2 = ffma2(wv[2 * i + 2], h1.x, a2);
            a3 = ffma2(wv[2 * i + 3], h1.y, a3);
        }
        a0 = ffma2(wv[24], ((const u64*)hp)[24], a0);
        u64 s2 = addf2(addf2(a0, a1), addf2(a2, a3));
        float glo, ghi;
        upk2(s2, glo, ghi);
        float g = glo + ghi;
        // per-gate activation BEFORE exchange (off the serial chain)
        float a = (q == 2) ? tanh_f(g) : sig_f(g);
        float af = __shfl_down_sync(0xffffffffu, a, 1);
        float ag = __shfl_down_sync(0xffffffffu, a, 2);
        float ao = __shfl_down_sync(0xffffffffu, a, 3);
        if (lead) {  // a = sig(i), af = sig(f), ag = tanh(g), ao = sig(o)
            c = af * c + a * ag;
            float hn = ao * tanh_f(c);
            hbuf[(S + 1) & 1][k] = hn;
            int t = t_start + sgn * S;
            if (t >= lo && t < hi) Hout[t * K1 + colbase] = hn;
        }
        __syncthreads();
    };

    float preA = ldpre(0);
    float preB = ldpre(1);
    for (int s = 0; s < ns; s += 2) {  // 2-deep prefetch of pre-gates stream
        step(s, preA);
        preA = ldpre(s + 2);
        if (s + 1 < ns) {
            step(s + 1, preB);
            preB = ldpre(s + 3);
        }
    }
}

// -------- per-token score vectors: ai[t]=h.w[:100]+b, sj[t]=h.w[100:] --------
__global__ __launch_bounds__(256) void score_vec(const float* __restrict__ mw,
                                                 const float* __restrict__ mb) {
    int t = blockIdx.x * 256 + threadIdx.x;
    const float* h = g_H1 + t * K1;
    float s1 = 0.f, s2 = 0.f;
#pragma unroll
    for (int dd = 0; dd < K1; dd++) {
        float hv = h[dd];
        s1 += hv * mw[dd];
        s2 += hv * mw[K1 + dd];
    }
    g_ai[t] = s1 + mb[0];
    g_sj[t] = s2;
}

// -------- NxN output, upper part only: out[i][j] = (j>i) ? tanh(ai+sj) : 0 ----
// Lower-triangle zeros were written by pre_gemm<0>'s interleaved zero blocks.
// 4 rows per block; each block starts at its rows' aligned boundary.
__global__ __launch_bounds__(256) void score_mat(float* __restrict__ out) {
    int i0 = blockIdx.x * 4;
    float a0 = g_ai[i0], a1 = g_ai[i0 + 1], a2 = g_ai[i0 + 2], a3 = g_ai[i0 + 3];
    const float4* sj4 = (const float4*)g_sj;
    int j4base = (i0 + 1) >> 2;  // covers [j4base*4, 8192) for rows i0..i0+3
    for (int j4 = j4base + threadIdx.x; j4 < NSEQ / 4; j4 += 256) {
        int col = j4 << 2;
        float4 s = sj4[j4];
#pragma unroll
        for (int r = 0; r < 4; r++) {
            int i = i0 + r;
            float a = (r == 0) ? a0 : (r == 1) ? a1 : (r == 2) ? a2 : a3;
            float4 v;
            v.x = (col > i) ? tanh_f(a + s.x) : 0.f;
            v.y = (col + 1 > i) ? tanh_f(a + s.y) : 0.f;
            v.z = (col + 2 > i) ? tanh_f(a + s.z) : 0.f;
            v.w = (col + 3 > i) ? tanh_f(a + s.w) : 0.f;
            *(float4*)(out + (size_t)i * NSEQ + col) = v;
        }
    }
}

extern "C" void kernel_launch(void* const* d_in, const int* in_sizes, int n_in,
                              void* d_out, int out_size) {
    const int* tok = (const int*)d_in[0];
    const float* pos = (const float*)d_in[1];
    const float* emb = (const float*)d_in[2];
    const float* wih0f = (const float*)d_in[3];
    const float* whh0f = (const float*)d_in[4];
    const float* b0f = (const float*)d_in[5];
    const float* wih0b = (const float*)d_in[6];
    const float* whh0b = (const float*)d_in[7];
    const float* b0b = (const float*)d_in[8];
    const float* wih1f = (const float*)d_in[9];
    const float* whh1f = (const float*)d_in[10];
    const float* b1f = (const float*)d_in[11];
    const float* wih1b = (const float*)d_in[12];
    const float* whh1b = (const float*)d_in[13];
    const float* b1b = (const float*)d_in[14];
    const float* mw = (const float*)d_in[15];
    const float* mb = (const float*)d_in[16];
    float* out = (float*)d_out;

    // layer0 pre-GEMM + interleaved lower-triangle zero-fill (1:4 mapping)
    pre_gemm<K0, 32, 0><<<NSEQ / 32 + ZBLK, 400>>>(tok, emb, pos, wih0f, wih0b,
                                                   b0f, b0b, out);
    lstm_scan<0><<<2 * NCHUNK, 224>>>(whh0f, whh0b);
    pre_gemm<K1, 64, 1><<<NSEQ / 64, 400>>>(tok, emb, pos, wih1f, wih1b, b1f,
                                            b1b, out);
    lstm_scan<1><<<2 * NCHUNK, 224>>>(whh1f, whh1b);
    score_vec<<<NSEQ / 256, 256>>>(mw, mb);
    score_mat<<<NSEQ / 4, 256>>>(out);
}

// round 16
// speedup vs baseline: 1.4756x; 1.0241x over previous
#include <cuda_runtime.h>

#define NSEQ 8192
#define HID 50
#define EDIM 300
#define PDIM 50
#define K0 350
#define K1 100
#define CH 64
#define BURN 40
#define NCHUNK (NSEQ / CH)

typedef unsigned long long u64;

// -------- scratch (no allocations allowed) --------
__device__ float g_P0[2u * NSEQ * 200];  // layer0 input-proj gates [dir][t][g]
__device__ float g_H0[NSEQ * K1];        // layer0 output concat [t][fwd50|bwd50]
__device__ float g_P1[2u * NSEQ * 200];
__device__ float g_H1[NSEQ * K1];
__device__ float g_ai[NSEQ];
__device__ float g_sj[NSEQ];

// -------- helpers --------
__device__ __forceinline__ u64 pk2(float lo, float hi) {
    u64 r;
    asm("mov.b64 %0,{%1,%2};" : "=l"(r) : "f"(lo), "f"(hi));
    return r;
}
__device__ __forceinline__ void upk2(u64 v, float& lo, float& hi) {
    asm("mov.b64 {%0,%1},%2;" : "=f"(lo), "=f"(hi) : "l"(v));
}
__device__ __forceinline__ u64 ffma2(u64 a, u64 b, u64 c) {
    u64 d;
    asm("fma.rn.f32x2 %0,%1,%2,%3;" : "=l"(d) : "l"(a), "l"(b), "l"(c));
    return d;
}
__device__ __forceinline__ u64 addf2(u64 a, u64 b) {
    u64 d;
    asm("add.rn.f32x2 %0,%1,%2;" : "=l"(d) : "l"(a), "l"(b));
    return d;
}
// accurate activations (EX2 + RCP, ~1e-6 rel): safe across the scan
__device__ __forceinline__ float sig_f(float x) {
    return __fdividef(1.f, 1.f + __expf(-x));
}
__device__ __forceinline__ float tanh_f(float x) {
    return __fdividef(2.f, 1.f + __expf(-2.f * x)) - 1.f;
}

// -------- input projection GEMM: P[dir][t][g] = b[g] + sum_k x[t][k]*W[g][k] --------
template <int KD, int TOK, int LAYER>
__global__ __launch_bounds__(400) void pre_gemm(
    const int* __restrict__ tok, const float* __restrict__ emb,
    const float* __restrict__ pos, const float* __restrict__ wf,
    const float* __restrict__ wb, const float* __restrict__ bf,
    const float* __restrict__ bb) {
    constexpr int XW = TOK + 4;  // keeps each row 16B-aligned (XW%4==0)
    __shared__ __align__(16) float xs[KD][XW];
    float* Pout = LAYER ? g_P1 : g_P0;
    int t0 = blockIdx.x * TOK;

    for (int idx = threadIdx.x; idx < KD * TOK; idx += 400) {
        int tt = idx / KD, k = idx - tt * KD;
        int t = t0 + tt;
        float v;
        if (LAYER == 0)
            v = (k < EDIM) ? emb[(size_t)tok[t] * EDIM + k]
                           : pos[t * PDIM + (k - EDIM)];
        else
            v = g_H0[t * K1 + k];
        xs[k][tt] = v;
    }
    __syncthreads();

    int o = threadIdx.x;
    int d = (o >= 200) ? 1 : 0;
    int oo = d ? o - 200 : o;
    const float* wr = (d ? wb : wf) + oo * KD;
    float bias = (d ? bb : bf)[oo];

    u64 acc[TOK / 2];
#pragma unroll
    for (int i = 0; i < TOK / 2; i++) acc[i] = 0ull;

    int kk = 0;
    // main loop: 4 k-values per iter, both weight LDGs issued up front (MLP>=2)
    for (; kk + 4 <= KD; kk += 4) {
        float2 wpA = __ldg((const float2*)(wr + kk));
        float2 wpB = __ldg((const float2*)(wr + kk + 2));
        u64 w0 = pk2(wpA.x, wpA.x);
        u64 w1 = pk2(wpA.y, wpA.y);
        u64 w2 = pk2(wpB.x, wpB.x);
        u64 w3 = pk2(wpB.y, wpB.y);
        const ulonglong2* x0 = (const ulonglong2*)(&xs[kk][0]);
        const ulonglong2* x1 = (const ulonglong2*)(&xs[kk + 1][0]);
        const ulonglong2* x2 = (const ulonglong2*)(&xs[kk + 2][0]);
        const ulonglong2* x3 = (const ulonglong2*)(&xs[kk + 3][0]);
#pragma unroll
        for (int i = 0; i < TOK / 4; i++) {
            ulonglong2 v0 = x0[i];
            acc[2 * i] = ffma2(w0, v0.x, acc[2 * i]);
            acc[2 * i + 1] = ffma2(w0, v0.y, acc[2 * i + 1]);
        }
#pragma unroll
        for (int i = 0; i < TOK / 4; i++) {
            ulonglong2 v1 = x1[i];
            acc[2 * i] = ffma2(w1, v1.x, acc[2 * i]);
            acc[2 * i + 1] = ffma2(w1, v1.y, acc[2 * i + 1]);
        }
#pragma unroll
        for (int i = 0; i < TOK / 4; i++) {
            ulonglong2 v2 = x2[i];
            acc[2 * i] = ffma2(w2, v2.x, acc[2 * i]);
            acc[2 * i + 1] = ffma2(w2, v2.y, acc[2 * i + 1]);
        }
#pragma unroll
        for (int i = 0; i < TOK / 4; i++) {
            ulonglong2 v3 = x3[i];
            acc[2 * i] = ffma2(w3, v3.x, acc[2 * i]);
            acc[2 * i + 1] = ffma2(w3, v3.y, acc[2 * i + 1]);
        }
    }
    for (; kk < KD; kk += 2) {  // remainder (KD=350 -> 2 left)
        float2 wp = __ldg((const float2*)(wr + kk));
        u64 w0 = pk2(wp.x, wp.x);
        u64 w1 = pk2(wp.y, wp.y);
        const ulonglong2* x0 = (const ulonglong2*)(&xs[kk][0]);
        const ulonglong2* x1 = (const ulonglong2*)(&xs[kk + 1][0]);
#pragma unroll
        for (int i = 0; i < TOK / 4; i++) {
            ulonglong2 v0 = x0[i];
            ulonglong2 v1 = x1[i];
            acc[2 * i] = ffma2(w0, v0.x, acc[2 * i]);
            acc[2 * i + 1] = ffma2(w0, v0.y, acc[2 * i + 1]);
            acc[2 * i] = ffma2(w1, v1.x, acc[2 * i]);
            acc[2 * i + 1] = ffma2(w1, v1.y, acc[2 * i + 1]);
        }
    }

    float* Po = Pout + ((size_t)d * NSEQ + t0) * 200 + oo;
#pragma unroll
    for (int i = 0; i < TOK / 2; i++) {
        float a, b2;
        upk2(acc[i], a, b2);
        Po[(2 * i) * 200] = a + bias;
        Po[(2 * i + 1) * 200] = b2 + bias;
    }
}

// -------- chunked LSTM scan with burn-in + free-running zero-fill warp -----
// grid = 2*NCHUNK blocks: block = (chunk, dir). 256 threads, 2 blocks/SM.
// Warps 0-6 (224 thr): LSTM scan, synced via named barrier 1 (count 224).
// Warp 7 (32 thr): never syncs — streams lower-triangle zeros of `out`
// under the scan's idle DRAM (2%), then exits.
// W_hh register-resident (R13 lesson: smem can't feed the MAC stream).
#define SCAN_BAR() asm volatile("bar.sync 1, 224;" ::: "memory")
template <int LAYER>
__global__ __launch_bounds__(256, 2) void lstm_scan(
    const float* __restrict__ whf, const float* __restrict__ whb,
    float* __restrict__ zout) {
    int tid = threadIdx.x;

    if (tid >= 224) {
        // ---- zero-fill warp: 16 strided rows of out's lower triangle ----
        int lane = tid - 224;
        int gid = LAYER * 256 + blockIdx.x;  // 0..511 unique across both scans
        float4 z = make_float4(0.f, 0.f, 0.f, 0.f);
#pragma unroll
        for (int j = 0; j < 16; j++) {
            int r = gid + (j << 9);          // rows gid, gid+512, ...
            int n4 = (r + 1) >> 2;           // float4 prefix with all cols <= r
            float4* row = (float4*)(zout + (size_t)r * NSEQ);
            for (int c = lane; c < n4; c += 32) row[c] = z;
        }
        return;
    }

    const float* P = LAYER ? g_P1 : g_P0;
    float* Hout = LAYER ? g_H1 : g_H0;

    int dir = blockIdx.x & 1;
    int chunk = blockIdx.x >> 1;
    int k = tid >> 2;
    if (k > HID - 1) k = HID - 1;  // clamp spare threads (no writes)
    int q = tid & 3;
    bool lead = (q == 0) && (tid < 4 * HID);

    const float* whh = dir ? whb : whf;
    u64 wv[HID / 2 + 1];  // 25 used
    {
        const u64* wrow = (const u64*)(whh + (q * HID + k) * HID);
#pragma unroll
        for (int j = 0; j < HID / 2; j++) wv[j] = wrow[j];
    }

    __shared__ __align__(16) float hbuf[2][64];  // double-buffered h
    if (tid < 64) { hbuf[0][tid] = 0.f; hbuf[1][tid] = 0.f; }
    float c = 0.f;

    int lo = chunk * CH, hi = lo + CH;
    int t_start, ns;
    if (!dir) {
        t_start = lo - BURN;
        if (t_start < 0) t_start = 0;
        ns = hi - t_start;
    } else {
        t_start = hi - 1 + BURN;
        if (t_start > NSEQ - 1) t_start = NSEQ - 1;
        ns = t_start - lo + 1;
    }
    int sgn = dir ? -1 : 1;
    const float* Pg = P + (size_t)dir * NSEQ * 200 + (q * HID + k);
    int colbase = dir * HID + k;
    SCAN_BAR();

    auto ldpre = [&](int s) -> float {
        return (s < ns) ? Pg[(size_t)(t_start + sgn * s) * 200] : 0.f;
    };
    auto step = [&](int S, float pre) {
        const ulonglong2* hp = (const ulonglong2*)hbuf[S & 1];
        // 4 independent accumulator chains; LDS.128 for h
        u64 a0 = pk2(pre, 0.f), a1 = 0ull, a2 = 0ull, a3 = 0ull;
#pragma unroll
        for (int i = 0; i < 12; i += 2) {
            ulonglong2 h0 = hp[i];
            ulonglong2 h1 = hp[i + 1];
            a0 = ffma2(wv[2 * i], h0.x, a0);
            a1 = ffma2(wv[2 * i + 1], h0.y, a1);
            a2 = ffma2(wv[2 * i + 2], h1.x, a2);
            a3 = ffma2(wv[2 * i + 3], h1.y, a3);
        }
        a0 = ffma2(wv[24], ((const u64*)hp)[24], a0);
        u64 s2 = addf2(addf2(a0, a1), addf2(a2, a3));
        float glo, ghi;
        upk2(s2, glo, ghi);
        float g = glo + ghi;
        // per-gate activation BEFORE exchange (off the serial chain)
        float a = (q == 2) ? tanh_f(g) : sig_f(g);
        float af = __shfl_down_sync(0xffffffffu, a, 1);
        float ag = __shfl_down_sync(0xffffffffu, a, 2);
        float ao = __shfl_down_sync(0xffffffffu, a, 3);
        if (lead) {  // a = sig(i), af = sig(f), ag = tanh(g), ao = sig(o)
            c = af * c + a * ag;
            float hn = ao * tanh_f(c);
            hbuf[(S + 1) & 1][k] = hn;
            int t = t_start + sgn * S;
            if (t >= lo && t < hi) Hout[t * K1 + colbase] = hn;
        }
        SCAN_BAR();
    };

    float preA = ldpre(0);
    float preB = ldpre(1);
    for (int s = 0; s < ns; s += 2) {  // 2-deep prefetch of pre-gates stream
        step(s, preA);
        preA = ldpre(s + 2);
        if (s + 1 < ns) {
            step(s + 1, preB);
            preB = ldpre(s + 3);
        }
    }
}

// -------- per-token score vectors: ai[t]=h.w[:100]+b, sj[t]=h.w[100:] --------
__global__ __launch_bounds__(256) void score_vec(const float* __restrict__ mw,
                                                 const float* __restrict__ mb) {
    int t = blockIdx.x * 256 + threadIdx.x;
    const float* h = g_H1 + t * K1;
    float s1 = 0.f, s2 = 0.f;
#pragma unroll
    for (int dd = 0; dd < K1; dd++) {
        float hv = h[dd];
        s1 += hv * mw[dd];
        s2 += hv * mw[K1 + dd];
    }
    g_ai[t] = s1 + mb[0];
    g_sj[t] = s2;
}

// -------- NxN output, upper part only: out[i][j] = (j>i) ? tanh(ai+sj) : 0 ----
// Lower-triangle zeros were written by the scans' zero-fill warps.
__global__ __launch_bounds__(256) void score_mat(float* __restrict__ out) {
    int i0 = blockIdx.x * 4;
    float a0 = g_ai[i0], a1 = g_ai[i0 + 1], a2 = g_ai[i0 + 2], a3 = g_ai[i0 + 3];
    const float4* sj4 = (const float4*)g_sj;
    int j4base = (i0 + 1) >> 2;  // covers [j4base*4, 8192) for rows i0..i0+3
    for (int j4 = j4base + threadIdx.x; j4 < NSEQ / 4; j4 += 256) {
        int col = j4 << 2;
        float4 s = sj4[j4];
#pragma unroll
        for (int r = 0; r < 4; r++) {
            int i = i0 + r;
            float a = (r == 0) ? a0 : (r == 1) ? a1 : (r == 2) ? a2 : a3;
            float4 v;
            v.x = (col > i) ? tanh_f(a + s.x) : 0.f;
            v.y = (col + 1 > i) ? tanh_f(a + s.y) : 0.f;
            v.z = (col + 2 > i) ? tanh_f(a + s.z) : 0.f;
            v.w = (col + 3 > i) ? tanh_f(a + s.w) : 0.f;
            *(float4*)(out + (size_t)i * NSEQ + col) = v;
        }
    }
}

extern "C" void kernel_launch(void* const* d_in, const int* in_sizes, int n_in,
                              void* d_out, int out_size) {
    const int* tok = (const int*)d_in[0];
    const float* pos = (const float*)d_in[1];
    const float* emb = (const float*)d_in[2];
    const float* wih0f = (const float*)d_in[3];
    const float* whh0f = (const float*)d_in[4];
    const float* b0f = (const float*)d_in[5];
    const float* wih0b = (const float*)d_in[6];
    const float* whh0b = (const float*)d_in[7];
    const float* b0b = (const float*)d_in[8];
    const float* wih1f = (const float*)d_in[9];
    const float* whh1f = (const float*)d_in[10];
    const float* b1f = (const float*)d_in[11];
    const float* wih1b = (const float*)d_in[12];
    const float* whh1b = (const float*)d_in[13];
    const float* b1b = (const float*)d_in[14];
    const float* mw = (const float*)d_in[15];
    const float* mb = (const float*)d_in[16];
    float* out = (float*)d_out;

    pre_gemm<K0, 32, 0><<<NSEQ / 32, 400>>>(tok, emb, pos, wih0f, wih0b, b0f,
                                            b0b);
    lstm_scan<0><<<2 * NCHUNK, 256>>>(whh0f, whh0b, out);
    pre_gemm<K1, 64, 1><<<NSEQ / 64, 400>>>(tok, emb, pos, wih1f, wih1b, b1f,
                                            b1b);
    lstm_scan<1><<<2 * NCHUNK, 256>>>(whh1f, whh1b, out);
    score_vec<<<NSEQ / 256, 256>>>(mw, mb);
    score_mat<<<NSEQ / 4, 256>>>(out);
}